// round 7
// baseline (speedup 1.0000x reference)
#include <cuda_runtime.h>
#include <stdint.h>

// TwoHotEmbedding: out[t,:] = w[i1[t],:]              if i1[t]==i2[t]
//                             w[i1[t],:] + w[i2[t],:]  otherwise
// B*S = 65536 tokens, D = 256 floats per row (1024 B).
//
// Model (R1-R6): pinned near the chip LTS-crossing cap (201 MB SM<->L2
// traffic @ ~8.3 TB/s). One-shot warps + small CTAs run the wall fastest;
// cache hints on loads bought nothing (hits and misses cost the same
// fabric bytes). R7 = R4 shape (2 tokens/warp, 256 thr, grid 4096, best
// e2e) + R1's plain unhinted gathers (best kernel time).

struct V8 { float4 a, b; };

__device__ __forceinline__ void stg_stream4(float* p, float4 v) {
    asm volatile("st.global.cs.v4.f32 [%0], {%1,%2,%3,%4};"
                 :: "l"(p), "f"(v.x), "f"(v.y), "f"(v.z), "f"(v.w)
                 : "memory");
}

__global__ __launch_bounds__(256) void twohot_kernel(
    const int* __restrict__ idx1,
    const int* __restrict__ idx2,
    const float* __restrict__ weight,   // [NUM_EMB, 256] f32
    float* __restrict__ out,            // [tokens, 256] f32
    int n_tokens)
{
    const int warp_global = (blockIdx.x * blockDim.x + threadIdx.x) >> 5;
    const int lane = threadIdx.x & 31;
    const int t0 = warp_global * 2;            // first of 2 tokens
    if (t0 >= n_tokens) return;

    // Paired index loads (64-bit each, warp-broadcast).
    const int2 ia = *(const int2*)(idx1 + t0);
    const int2 ib = *(const int2*)(idx2 + t0);

    const int off = lane * 8;                  // 8 floats = 32 B per lane
    const float4* p1a = (const float4*)(weight + (size_t)ia.x * 256 + off);
    const float4* p2a = (const float4*)(weight + (size_t)ib.x * 256 + off);
    const float4* p1b = (const float4*)(weight + (size_t)ia.y * 256 + off);
    const float4* p2b = (const float4*)(weight + (size_t)ib.y * 256 + off);

    // 8 independent 128-bit gathers in flight (plain, unhinted — fastest
    // form measured).
    float4 e1a0 = __ldg(p1a);     float4 e1a1 = __ldg(p1a + 1);
    float4 e2a0 = __ldg(p2a);     float4 e2a1 = __ldg(p2a + 1);
    float4 e1b0 = __ldg(p1b);     float4 e1b1 = __ldg(p1b + 1);
    float4 e2b0 = __ldg(p2b);     float4 e2b1 = __ldg(p2b + 1);

    // i1==i2 has probability ~1e-5: handle with selects, no divergence.
    const bool sa = (ia.x == ib.x);
    const bool sb = (ia.y == ib.y);

    float4 ra0, ra1, rb0, rb1;
    ra0.x = sa ? e1a0.x : e1a0.x + e2a0.x;  ra0.y = sa ? e1a0.y : e1a0.y + e2a0.y;
    ra0.z = sa ? e1a0.z : e1a0.z + e2a0.z;  ra0.w = sa ? e1a0.w : e1a0.w + e2a0.w;
    ra1.x = sa ? e1a1.x : e1a1.x + e2a1.x;  ra1.y = sa ? e1a1.y : e1a1.y + e2a1.y;
    ra1.z = sa ? e1a1.z : e1a1.z + e2a1.z;  ra1.w = sa ? e1a1.w : e1a1.w + e2a1.w;
    rb0.x = sb ? e1b0.x : e1b0.x + e2b0.x;  rb0.y = sb ? e1b0.y : e1b0.y + e2b0.y;
    rb0.z = sb ? e1b0.z : e1b0.z + e2b0.z;  rb0.w = sb ? e1b0.w : e1b0.w + e2b0.w;
    rb1.x = sb ? e1b1.x : e1b1.x + e2b1.x;  rb1.y = sb ? e1b1.y : e1b1.y + e2b1.y;
    rb1.z = sb ? e1b1.z : e1b1.z + e2b1.z;  rb1.w = sb ? e1b1.w : e1b1.w + e2b1.w;

    float* oa = out + (size_t)t0 * 256 + off;
    float* ob = oa + 256;
    stg_stream4(oa,     ra0);
    stg_stream4(oa + 4, ra1);
    stg_stream4(ob,     rb0);
    stg_stream4(ob + 4, rb1);
}

extern "C" void kernel_launch(void* const* d_in, const int* in_sizes, int n_in,
                              void* d_out, int out_size)
{
    const int* idx1 = (const int*)d_in[0];        // input_one [B,S] int32
    const int* idx2 = (const int*)d_in[1];        // input_two [B,S] int32
    const float* weight = (const float*)d_in[2];  // weight [100000,256] f32

    float* out = (float*)d_out;

    const int n_tokens = in_sizes[0];             // 65536
    (void)n_in; (void)out_size;

    // 8 warps/block, 2 tokens/warp -> 16 tokens/block -> 4096 blocks.
    const int tokens_per_block = 16;
    const int blocks = (n_tokens + tokens_per_block - 1) / tokens_per_block;
    twohot_kernel<<<blocks, 256>>>(idx1, idx2, weight, out, n_tokens);
}

// round 8
// speedup vs baseline: 1.0590x; 1.0590x over previous
#include <cuda_runtime.h>
#include <stdint.h>

// TwoHotEmbedding: out[t,:] = w[i1[t],:]              if i1[t]==i2[t]
//                             w[i1[t],:] + w[i2[t],:]  otherwise
// B*S = 65536 tokens, D = 256 floats per row (1024 B = 32 lanes x 32 B).
//
// Model (R1-R7): pinned by L2 sector-access throughput (~6.3M sectors over
// 192 LTS slices ~ 20us @NAT) -- path-independent of hit/miss, so cache
// hints move DRAM bytes but never time. v8 (256-bit) gathers beat 2x128-bit
// at equal shape. 2tok/warp halves the grid (smallest e2e launch gap, 1.4us
// @4096 blocks). R8 = R4 + reg-pressure fix (launch_bounds(256,8), 32-bit
// address math) to recover the ~1us occupancy-ramp loss.

struct V8 { float v[8]; };

__device__ __forceinline__ V8 ldg256_keep(const float* p) {
    V8 r;
    asm volatile(
        "ld.global.nc.L2::evict_last.v8.b32 {%0,%1,%2,%3,%4,%5,%6,%7}, [%8];"
        : "=f"(r.v[0]), "=f"(r.v[1]), "=f"(r.v[2]), "=f"(r.v[3]),
          "=f"(r.v[4]), "=f"(r.v[5]), "=f"(r.v[6]), "=f"(r.v[7])
        : "l"(p));
    return r;
}

__device__ __forceinline__ void stg_stream4(float* p, float a, float b, float c, float d) {
    asm volatile("st.global.cs.v4.f32 [%0], {%1,%2,%3,%4};"
                 :: "l"(p), "f"(a), "f"(b), "f"(c), "f"(d)
                 : "memory");
}

__global__ __launch_bounds__(256, 8) void twohot_kernel(
    const int* __restrict__ idx1,
    const int* __restrict__ idx2,
    const float* __restrict__ weight,   // [NUM_EMB, 256] f32
    float* __restrict__ out,            // [tokens, 256] f32
    int n_tokens)
{
    const int warp_global = (blockIdx.x * blockDim.x + threadIdx.x) >> 5;
    const unsigned lane = threadIdx.x & 31;
    const int t0 = warp_global * 2;            // first of 2 tokens
    if (t0 >= n_tokens) return;

    // Paired index loads (64-bit each, warp-broadcast).
    const int2 ia = *(const int2*)(idx1 + t0);
    const int2 ib = *(const int2*)(idx2 + t0);

    // 32-bit element offsets: idx < 100000, idx*256 + 255 < 2^25 (safe).
    const unsigned off = lane * 8u;            // 8 floats = 32 B per lane
    const float* p1a = weight + ((unsigned)ia.x * 256u + off);
    const float* p2a = weight + ((unsigned)ib.x * 256u + off);
    const float* p1b = weight + ((unsigned)ia.y * 256u + off);
    const float* p2b = weight + ((unsigned)ib.y * 256u + off);

    // 4 independent 256-bit gathers in flight.
    V8 e1a = ldg256_keep(p1a);
    V8 e2a = ldg256_keep(p2a);
    V8 e1b = ldg256_keep(p1b);
    V8 e2b = ldg256_keep(p2b);

    // i1==i2 has probability ~1e-5: handle with selects, no divergence.
    const bool sa = (ia.x == ib.x);
    const bool sb = (ia.y == ib.y);

    float ra[8], rb[8];
    #pragma unroll
    for (int i = 0; i < 8; i++) {
        ra[i] = sa ? e1a.v[i] : e1a.v[i] + e2a.v[i];
        rb[i] = sb ? e1b.v[i] : e1b.v[i] + e2b.v[i];
    }

    float* oa = out + ((unsigned)t0 * 256u + off);   // t0*256 < 2^25, safe
    float* ob = oa + 256;
    stg_stream4(oa,     ra[0], ra[1], ra[2], ra[3]);
    stg_stream4(oa + 4, ra[4], ra[5], ra[6], ra[7]);
    stg_stream4(ob,     rb[0], rb[1], rb[2], rb[3]);
    stg_stream4(ob + 4, rb[4], rb[5], rb[6], rb[7]);
}

extern "C" void kernel_launch(void* const* d_in, const int* in_sizes, int n_in,
                              void* d_out, int out_size)
{
    const int* idx1 = (const int*)d_in[0];        // input_one [B,S] int32
    const int* idx2 = (const int*)d_in[1];        // input_two [B,S] int32
    const float* weight = (const float*)d_in[2];  // weight [100000,256] f32

    float* out = (float*)d_out;

    const int n_tokens = in_sizes[0];             // 65536
    (void)n_in; (void)out_size;

    // 8 warps/block, 2 tokens/warp -> 16 tokens/block -> 4096 blocks.
    const int tokens_per_block = 16;
    const int blocks = (n_tokens + tokens_per_block - 1) / tokens_per_block;
    twohot_kernel<<<blocks, 256>>>(idx1, idx2, weight, out, n_tokens);
}

// round 9
// speedup vs baseline: 1.0780x; 1.0180x over previous
#include <cuda_runtime.h>
#include <stdint.h>

// TwoHotEmbedding: out[t,:] = w[i1[t],:]              if i1[t]==i2[t]
//                             w[i1[t],:] + w[i2[t],:]  otherwise
// B*S = 65536 tokens, D = 256 floats per row (1024 B = 32 lanes x 32 B).
//
// Converged model (R1-R8): kernel pinned at the path-independent chip LTS
// cap (~200 MB SM<->L2 traffic @ ~8.3 TB/s => ~24-25.5us) -- invariant
// under occupancy (59-81%), DRAM bytes (105-115MB), load width, cache
// hints, and (per B300_MICROARCH, cap is "LDG.cv == TMA") would also be
// invariant under a TMA rewrite. Gather traffic is algorithmically
// incompressible. This is the empirically best configuration (R4): one-shot
// 2 tokens/warp, 4 independent 256-bit evict_last gathers in flight,
// streaming .cs stores, 256-thread CTAs, grid 4096.

struct V8 { float v[8]; };

__device__ __forceinline__ V8 ldg256_keep(const float* p) {
    V8 r;
    asm volatile(
        "ld.global.nc.L2::evict_last.v8.b32 {%0,%1,%2,%3,%4,%5,%6,%7}, [%8];"
        : "=f"(r.v[0]), "=f"(r.v[1]), "=f"(r.v[2]), "=f"(r.v[3]),
          "=f"(r.v[4]), "=f"(r.v[5]), "=f"(r.v[6]), "=f"(r.v[7])
        : "l"(p));
    return r;
}

__device__ __forceinline__ void stg_stream4(float* p, float a, float b, float c, float d) {
    asm volatile("st.global.cs.v4.f32 [%0], {%1,%2,%3,%4};"
                 :: "l"(p), "f"(a), "f"(b), "f"(c), "f"(d)
                 : "memory");
}

__global__ __launch_bounds__(256) void twohot_kernel(
    const int* __restrict__ idx1,
    const int* __restrict__ idx2,
    const float* __restrict__ weight,   // [NUM_EMB, 256] f32
    float* __restrict__ out,            // [tokens, 256] f32
    int n_tokens)
{
    const int warp_global = (blockIdx.x * blockDim.x + threadIdx.x) >> 5;
    const int lane = threadIdx.x & 31;
    const int t0 = warp_global * 2;            // first of 2 tokens
    if (t0 >= n_tokens) return;

    // Paired index loads (64-bit each, warp-broadcast).
    const int2 ia = *(const int2*)(idx1 + t0);
    const int2 ib = *(const int2*)(idx2 + t0);

    const int off = lane * 8;
    const float* p1a = weight + (size_t)ia.x * 256 + off;
    const float* p2a = weight + (size_t)ib.x * 256 + off;
    const float* p1b = weight + (size_t)ia.y * 256 + off;
    const float* p2b = weight + (size_t)ib.y * 256 + off;

    // 4 independent 256-bit gathers in flight.
    V8 e1a = ldg256_keep(p1a);
    V8 e2a = ldg256_keep(p2a);
    V8 e1b = ldg256_keep(p1b);
    V8 e2b = ldg256_keep(p2b);

    // i1==i2 has probability ~1e-5: handle with selects, no divergence.
    const bool same_a = (ia.x == ib.x);
    const bool same_b = (ia.y == ib.y);

    float ra[8], rb[8];
    #pragma unroll
    for (int i = 0; i < 8; i++) {
        ra[i] = same_a ? e1a.v[i] : e1a.v[i] + e2a.v[i];
        rb[i] = same_b ? e1b.v[i] : e1b.v[i] + e2b.v[i];
    }

    float* oa = out + (size_t)t0 * 256 + off;
    float* ob = oa + 256;
    stg_stream4(oa,     ra[0], ra[1], ra[2], ra[3]);
    stg_stream4(oa + 4, ra[4], ra[5], ra[6], ra[7]);
    stg_stream4(ob,     rb[0], rb[1], rb[2], rb[3]);
    stg_stream4(ob + 4, rb[4], rb[5], rb[6], rb[7]);
}

extern "C" void kernel_launch(void* const* d_in, const int* in_sizes, int n_in,
                              void* d_out, int out_size)
{
    const int* idx1 = (const int*)d_in[0];        // input_one [B,S] int32
    const int* idx2 = (const int*)d_in[1];        // input_two [B,S] int32
    const float* weight = (const float*)d_in[2];  // weight [100000,256] f32

    float* out = (float*)d_out;

    const int n_tokens = in_sizes[0];             // 65536
    (void)n_in; (void)out_size;

    // 8 warps/block, 2 tokens/warp -> 16 tokens per block -> 4096 blocks.
    const int tokens_per_block = 16;
    const int blocks = (n_tokens + tokens_per_block - 1) / tokens_per_block;
    twohot_kernel<<<blocks, 256>>>(idx1, idx2, weight, out, n_tokens);
}